// round 3
// baseline (speedup 1.0000x reference)
#include <cuda_runtime.h>

#define Bn 256
#define Sn 64
#define Dn 64
#define Fn 10
#define NCn 10
#define Pf 2016.0f

struct __align__(16) Smem {
    float E[Sn * Dn];       // embeddings           4096
    float U[Sn * Dn];       // E@W1a + b1, later FH 4096
    float V[Sn * Dn];       // E@W1b                4096
    float W[65 * Dn];       // staging: W1a/W1b/freq_w1
    float cw2[Dn * Fn];     // comb_w2
    float fw2[Dn * Fn];     // freq_w2
    float cc[NCn * Dn];     // cluster centers
    float fr[Sn];           // per-token frequency
    float e2s[Sn];          // |e_s|^2
    float cn2[16];          // |c|^2
    float Hpart[4 * Dn];    // partial pair sums
    float Hsum[Dn];
    float csum[16];         // combo_sum (incl P*b2)
    float dist[Sn * NCn];   // distances -> softmax in place
    int   sid[Sn];
};

__device__ __forceinline__ void gemm16(const float4* __restrict__ E4,
                                       const float4* __restrict__ W4,
                                       int s0, int dblk, float acc[4][4]) {
#pragma unroll
    for (int kk = 0; kk < 16; ++kk) {
        float4 w0 = W4[(4 * kk + 0) * 16 + dblk];
        float4 w1 = W4[(4 * kk + 1) * 16 + dblk];
        float4 w2 = W4[(4 * kk + 2) * 16 + dblk];
        float4 w3 = W4[(4 * kk + 3) * 16 + dblk];
#pragma unroll
        for (int si = 0; si < 4; ++si) {
            float4 e = E4[(s0 + si) * 16 + kk];
            acc[si][0] += e.x * w0.x + e.y * w1.x + e.z * w2.x + e.w * w3.x;
            acc[si][1] += e.x * w0.y + e.y * w1.y + e.z * w2.y + e.w * w3.y;
            acc[si][2] += e.x * w0.z + e.y * w1.z + e.z * w2.z + e.w * w3.z;
            acc[si][3] += e.x * w0.w + e.y * w1.w + e.z * w2.w + e.w * w3.w;
        }
    }
}

__global__ __launch_bounds__(256, 2)
void cate_enc_kernel(const int* __restrict__ ids, const float* __restrict__ table,
                     const float* __restrict__ cw1, const float* __restrict__ cb1,
                     const float* __restrict__ cw2g, const float* __restrict__ cb2,
                     const float* __restrict__ fw1, const float* __restrict__ fb1,
                     const float* __restrict__ fw2g, const float* __restrict__ fb2,
                     const float* __restrict__ ccg, const float* __restrict__ catf,
                     const float* __restrict__ tot, float* __restrict__ out) {
    extern __shared__ char smraw[];
    Smem& sm = *reinterpret_cast<Smem*>(smraw);
    const int t = threadIdx.x;
    const int b = blockIdx.x;

    // ---- phase 0a: ids + freqs, stage W1a and small weights ----
    if (t < Sn) {
        int id = ids[b * Sn + t];
        sm.sid[t] = id;
        sm.fr[t] = catf[id] / tot[0];
    }
    {
        float4* W4 = (float4*)sm.W;
        const float4* g4 = (const float4*)cw1;   // rows 0..63 = W1a
#pragma unroll
        for (int c = 0; c < 4; ++c) W4[t + 256 * c] = g4[t + 256 * c];
        if (t < 160) {
            ((float4*)sm.cw2)[t] = ((const float4*)cw2g)[t];
            ((float4*)sm.fw2)[t] = ((const float4*)fw2g)[t];
            ((float4*)sm.cc)[t]  = ((const float4*)ccg)[t];
        }
    }
    __syncthreads();

    // ---- phase 0b: embedding gather (float4, 16 per row) ----
    {
        float4* E4 = (float4*)sm.E;
        const float4* T4 = (const float4*)table;
#pragma unroll
        for (int c = 0; c < 4; ++c) {
            int lin = t + 256 * c;
            int s = lin >> 4, q = lin & 15;
            E4[lin] = T4[sm.sid[s] * 16 + q];
        }
    }
    __syncthreads();

    const int sblk = t >> 4, dblk = t & 15;
    const int s0 = sblk * 4;

    // ---- phase 1: U = E @ W1a + b1 ----
    {
        float acc[4][4] = {};
        gemm16((const float4*)sm.E, (const float4*)sm.W, s0, dblk, acc);
        float4 bv = ((const float4*)cb1)[dblk];
        float4* U4 = (float4*)sm.U;
#pragma unroll
        for (int si = 0; si < 4; ++si) {
            float4 o;
            o.x = acc[si][0] + bv.x; o.y = acc[si][1] + bv.y;
            o.z = acc[si][2] + bv.z; o.w = acc[si][3] + bv.w;
            U4[(s0 + si) * 16 + dblk] = o;
        }
    }
    __syncthreads();

    // ---- phase 2: stage W1b ----
    {
        float4* W4 = (float4*)sm.W;
        const float4* g4 = (const float4*)cw1;
#pragma unroll
        for (int c = 0; c < 4; ++c) W4[t + 256 * c] = g4[1024 + t + 256 * c];
    }
    __syncthreads();

    // ---- phase 3: V = E @ W1b ----
    {
        float acc[4][4] = {};
        gemm16((const float4*)sm.E, (const float4*)sm.W, s0, dblk, acc);
        float4* V4 = (float4*)sm.V;
#pragma unroll
        for (int si = 0; si < 4; ++si) {
            float4 o;
            o.x = acc[si][0]; o.y = acc[si][1]; o.z = acc[si][2]; o.w = acc[si][3];
            V4[(s0 + si) * 16 + dblk] = o;
        }
    }
    __syncthreads();

    // ---- phase 4: stage freq_w1 (65 rows); pair sum overlaps load latency ----
    {
        float4* W4 = (float4*)sm.W;
        const float4* g4 = (const float4*)fw1;
#pragma unroll
        for (int c = 0; c < 4; ++c) W4[t + 256 * c] = g4[t + 256 * c];
        if (t < 16) W4[1024 + t] = g4[1024 + t];
    }
    {
        const int d = t & 63, q = t >> 6;
        float acc = 0.f;
        for (int i = q; i < Sn; i += 4) {
            float a = sm.U[i * Dn + d];
#pragma unroll 4
            for (int j = i + 1; j < Sn; ++j)
                acc += fmaxf(a + sm.V[j * Dn + d], 0.f);
        }
        sm.Hpart[q * Dn + d] = acc;
    }
    __syncthreads();

    // ---- phase 5: reduce Hsum, |e|^2, |c|^2 ----
    if (t < Sn) {
        sm.Hsum[t] = sm.Hpart[t] + sm.Hpart[64 + t] + sm.Hpart[128 + t] + sm.Hpart[192 + t];
        const float4* E4 = (const float4*)sm.E;
        float s2 = 0.f;
#pragma unroll
        for (int kk = 0; kk < 16; ++kk) {
            float4 e = E4[t * 16 + kk];
            s2 += e.x * e.x + e.y * e.y + e.z * e.z + e.w * e.w;
        }
        sm.e2s[t] = s2;
    } else if (t < Sn + NCn) {
        int c = t - Sn;
        const float4* C4 = (const float4*)sm.cc;
        float s2 = 0.f;
#pragma unroll
        for (int kk = 0; kk < 16; ++kk) {
            float4 e = C4[c * 16 + kk];
            s2 += e.x * e.x + e.y * e.y + e.z * e.z + e.w * e.w;
        }
        sm.cn2[c] = s2;
    }
    __syncthreads();

    // ---- phase 6: FH = relu(E@fw1[:64] + fr*fw1[64] + fb1) -> U; distances; csum ----
    {
        float acc[4][4] = {};
        gemm16((const float4*)sm.E, (const float4*)sm.W, s0, dblk, acc);
        float4 fbv = ((const float4*)fb1)[dblk];
        float4 wl  = ((const float4*)(sm.W + 64 * Dn))[dblk];
        float4* U4 = (float4*)sm.U;
#pragma unroll
        for (int si = 0; si < 4; ++si) {
            float fq = sm.fr[s0 + si];
            float4 o;
            o.x = fmaxf(acc[si][0] + fq * wl.x + fbv.x, 0.f);
            o.y = fmaxf(acc[si][1] + fq * wl.y + fbv.y, 0.f);
            o.z = fmaxf(acc[si][2] + fq * wl.z + fbv.z, 0.f);
            o.w = fmaxf(acc[si][3] + fq * wl.w + fbv.w, 0.f);
            U4[(s0 + si) * 16 + dblk] = o;
        }
    }
    {
        const int s = t & 63, g = t >> 6;
        const float4* E4 = (const float4*)sm.E;
        const float4* C4 = (const float4*)sm.cc;
        for (int c = g; c < NCn; c += 4) {
            float dot = 0.f;
#pragma unroll
            for (int kk = 0; kk < 16; ++kk) {
                float4 e = E4[s * 16 + kk];
                float4 cv = C4[c * 16 + kk];
                dot += e.x * cv.x + e.y * cv.y + e.z * cv.z + e.w * cv.w;
            }
            float d2 = sm.e2s[s] + sm.cn2[c] - 2.f * dot;
            sm.dist[s * NCn + c] = sqrtf(fmaxf(d2, 0.f));
        }
    }
    if (t < NCn) {
        float s = 0.f;
#pragma unroll 8
        for (int d = 0; d < Dn; ++d) s += sm.Hsum[d] * sm.cw2[d * Fn + t];
        sm.csum[t] = s + Pf * cb2[t];
    }
    __syncthreads();

    // ---- phase 7: softmax(-dist) per token ----
    if (t < Sn) {
        float mn = sm.dist[t * NCn];
#pragma unroll
        for (int c = 1; c < NCn; ++c) mn = fminf(mn, sm.dist[t * NCn + c]);
        float e[NCn]; float ssum = 0.f;
#pragma unroll
        for (int c = 0; c < NCn; ++c) { e[c] = __expf(mn - sm.dist[t * NCn + c]); ssum += e[c]; }
        float inv = 1.f / ssum;
#pragma unroll
        for (int c = 0; c < NCn; ++c) sm.dist[t * NCn + c] = e[c] * inv;
    }
    __syncthreads();

    // ---- phase 8: final output ----
    const float invP = 1.f / (Pf + 2.f);
    for (int lin = t; lin < Sn * Fn; lin += 256) {
        int s = lin / Fn, f = lin - s * Fn;
        float ff = 0.f;
#pragma unroll 8
        for (int d = 0; d < Dn; ++d) ff += sm.U[s * Dn + d] * sm.fw2[d * Fn + f];
        out[b * (Sn * Fn) + lin] = (ff + fb2[f] + sm.csum[f] + sm.dist[lin]) * invP;
    }
}

extern "C" void kernel_launch(void* const* d_in, const int* in_sizes, int n_in,
                              void* d_out, int out_size) {
    const int*   ids  = (const int*)d_in[0];
    const float* tab  = (const float*)d_in[1];
    const float* cw1  = (const float*)d_in[2];
    const float* cb1  = (const float*)d_in[3];
    const float* cw2  = (const float*)d_in[4];
    const float* cb2  = (const float*)d_in[5];
    const float* fw1  = (const float*)d_in[6];
    const float* fb1  = (const float*)d_in[7];
    const float* fw2  = (const float*)d_in[8];
    const float* fb2  = (const float*)d_in[9];
    const float* cc   = (const float*)d_in[10];
    const float* catf = (const float*)d_in[11];
    const float* tot  = (const float*)d_in[12];
    float* out = (float*)d_out;

    cudaFuncSetAttribute(cate_enc_kernel,
                         cudaFuncAttributeMaxDynamicSharedMemorySize,
                         (int)sizeof(Smem));
    cate_enc_kernel<<<Bn, 256, sizeof(Smem)>>>(ids, tab, cw1, cb1, cw2, cb2,
                                               fw1, fb1, fw2, fb2, cc, catf,
                                               tot, out);
}